// round 6
// baseline (speedup 1.0000x reference)
#include <cuda_runtime.h>
#include <math.h>

#define NP 768
#define DD 128
#define HH 8

// ---- scratch (no allocs allowed; static device globals) ----
__device__ float g_G [NP*NP];
__device__ float g_VE[NP*NP];
__device__ float g_SE[NP*NP];
__device__ float g_LG[NP*NP];
__device__ float g_P [NP*DD];
__device__ float g_M [NP*DD];
__device__ float g_S8[NP*HH];
__device__ float g_NRM[NP];

// ================= X @ X^T (Gram matrix), K = 128 or 312 =================
__global__ __launch_bounds__(256) void xxt_kernel(const float* __restrict__ X, int K,
                                                  float* __restrict__ G) {
    __shared__ float Xi[32][33];
    __shared__ float Xk[32][33];
    int bi = blockIdx.y * 32, bk = blockIdx.x * 32;
    int t = threadIdx.x, tx = t & 15, ty = t >> 4;
    float a00 = 0.f, a01 = 0.f, a10 = 0.f, a11 = 0.f;
    for (int k0 = 0; k0 < K; k0 += 32) {
        for (int idx = t; idx < 1024; idx += 256) {
            int r = idx >> 5, c = idx & 31;
            int kc = k0 + c;
            float vi = (kc < K) ? X[(bi + r) * K + kc] : 0.f;
            float vk = (kc < K) ? X[(bk + r) * K + kc] : 0.f;
            Xi[r][c] = vi;
            Xk[r][c] = vk;
        }
        __syncthreads();
#pragma unroll
        for (int kk = 0; kk < 32; kk++) {
            float x0 = Xi[2 * ty][kk], x1 = Xi[2 * ty + 1][kk];
            float y0 = Xk[2 * tx][kk], y1 = Xk[2 * tx + 1][kk];
            a00 += x0 * y0; a01 += x0 * y1;
            a10 += x1 * y0; a11 += x1 * y1;
        }
        __syncthreads();
    }
    G[(bi + 2 * ty) * NP + bk + 2 * tx]         = a00;
    G[(bi + 2 * ty) * NP + bk + 2 * tx + 1]     = a01;
    G[(bi + 2 * ty + 1) * NP + bk + 2 * tx]     = a10;
    G[(bi + 2 * ty + 1) * NP + bk + 2 * tx + 1] = a11;
}

__global__ void norms_kernel(const float* __restrict__ G, float* __restrict__ nrm) {
    int i = blockIdx.x * 256 + threadIdx.x;
    if (i < NP) nrm[i] = sqrtf(G[i * NP + i]);
}

// ============ row softmax of cosine-sim logits from Gram matrix ============
__global__ __launch_bounds__(256) void softmax_sim_kernel(const float* __restrict__ G,
                                                          const float* __restrict__ nrm,
                                                          float invtemp,
                                                          float* __restrict__ E) {
    __shared__ float sh[256];
    int i = blockIdx.x, t = threadIdx.x;
    float ni = nrm[i];
    float l[3];
    float mx = -1e30f;
#pragma unroll
    for (int q = 0; q < 3; q++) {
        int c = t + q * 256;
        float den = fmaxf(ni * nrm[c], 1e-8f);
        l[q] = G[i * NP + c] / den * invtemp;
        mx = fmaxf(mx, l[q]);
    }
    sh[t] = mx; __syncthreads();
    for (int s = 128; s > 0; s >>= 1) { if (t < s) sh[t] = fmaxf(sh[t], sh[t + s]); __syncthreads(); }
    mx = sh[0]; __syncthreads();
    float sum = 0.f;
#pragma unroll
    for (int q = 0; q < 3; q++) { l[q] = expf(l[q] - mx); sum += l[q]; }
    sh[t] = sum; __syncthreads();
    for (int s = 128; s > 0; s >>= 1) { if (t < s) sh[t] += sh[t + s]; __syncthreads(); }
    float inv = 1.f / sh[0];
#pragma unroll
    for (int q = 0; q < 3; q++) E[i * NP + t + q * 256] = l[q] * inv;
}

// ================= plain row softmax of precomputed logits =================
__global__ __launch_bounds__(256) void softmax_row_kernel(const float* __restrict__ LGin,
                                                          float* __restrict__ E) {
    __shared__ float sh[256];
    int i = blockIdx.x, t = threadIdx.x;
    float l[3];
    float mx = -1e30f;
#pragma unroll
    for (int q = 0; q < 3; q++) { l[q] = LGin[i * NP + t + q * 256]; mx = fmaxf(mx, l[q]); }
    sh[t] = mx; __syncthreads();
    for (int s = 128; s > 0; s >>= 1) { if (t < s) sh[t] = fmaxf(sh[t], sh[t + s]); __syncthreads(); }
    mx = sh[0]; __syncthreads();
    float sum = 0.f;
#pragma unroll
    for (int q = 0; q < 3; q++) { l[q] = expf(l[q] - mx); sum += l[q]; }
    sh[t] = sum; __syncthreads();
    for (int s = 128; s > 0; s >>= 1) { if (t < s) sh[t] += sh[t + s]; __syncthreads(); }
    float inv = 1.f / sh[0];
#pragma unroll
    for (int q = 0; q < 3; q++) E[i * NP + t + q * 256] = l[q] * inv;
}

// ===== aggregation: P = E @ V ; M = (E + L) @ V   (M=768, N=128, K=768) =====
__global__ __launch_bounds__(256) void agg_kernel(const float* __restrict__ E,
                                                  const float* __restrict__ L,
                                                  const float* __restrict__ V,
                                                  float* __restrict__ Pout,
                                                  float* __restrict__ Mout) {
    __shared__ float Es[32][33];
    __shared__ float Ls[32][33];
    __shared__ float Vs[32][128];
    int bi = blockIdx.x * 32;
    int t = threadIdx.x, tx = t & 31, ty = t >> 5;
    float accP[4][4], accM[4][4];
#pragma unroll
    for (int r = 0; r < 4; r++)
#pragma unroll
        for (int c = 0; c < 4; c++) { accP[r][c] = 0.f; accM[r][c] = 0.f; }

    for (int k0 = 0; k0 < NP; k0 += 32) {
        for (int idx = t; idx < 1024; idx += 256) {
            int r = idx >> 5, c = idx & 31;
            Es[r][c] = E[(bi + r) * NP + k0 + c];
            Ls[r][c] = L[(bi + r) * NP + k0 + c];
        }
        for (int idx = t; idx < 1024; idx += 256) {
            int r = idx >> 5, c4 = idx & 31;
            *(float4*)&Vs[r][c4 * 4] = *(const float4*)&V[(k0 + r) * DD + c4 * 4];
        }
        __syncthreads();
#pragma unroll 8
        for (int kk = 0; kk < 32; kk++) {
            float4 v = *(const float4*)&Vs[kk][tx * 4];
#pragma unroll
            for (int r = 0; r < 4; r++) {
                float e = Es[ty * 4 + r][kk];
                float m = e + Ls[ty * 4 + r][kk];
                accP[r][0] += e * v.x; accP[r][1] += e * v.y;
                accP[r][2] += e * v.z; accP[r][3] += e * v.w;
                accM[r][0] += m * v.x; accM[r][1] += m * v.y;
                accM[r][2] += m * v.z; accM[r][3] += m * v.w;
            }
        }
        __syncthreads();
    }
#pragma unroll
    for (int r = 0; r < 4; r++) {
        int row = bi + ty * 4 + r;
        *(float4*)&Pout[row * DD + tx * 4] = make_float4(accP[r][0], accP[r][1], accP[r][2], accP[r][3]);
        *(float4*)&Mout[row * DD + tx * 4] = make_float4(accM[r][0], accM[r][1], accM[r][2], accM[r][3]);
    }
}

// ======== node update: out = relu(LN(M @ W^T + b, g, beta)) + P  ========
__global__ __launch_bounds__(128) void node_kernel(const float* __restrict__ Mi,
                                                   const float* __restrict__ Pi,
                                                   const float* __restrict__ W,
                                                   const float* __restrict__ bv,
                                                   const float* __restrict__ gv,
                                                   const float* __restrict__ bev,
                                                   float* __restrict__ outp) {
    __shared__ float ms[128];
    __shared__ float red[128];
    int i = blockIdx.x, o = threadIdx.x;
    ms[o] = Mi[i * DD + o];
    __syncthreads();
    float acc = bv[o];
    const float4* w4 = (const float4*)(W + o * DD);
    const float4* m4 = (const float4*)ms;
#pragma unroll
    for (int q = 0; q < 32; q++) {
        float4 w = w4[q];
        float4 m = m4[q];
        acc += w.x * m.x + w.y * m.y + w.z * m.z + w.w * m.w;
    }
    red[o] = acc; __syncthreads();
    for (int s = 64; s > 0; s >>= 1) { if (o < s) red[o] += red[o + s]; __syncthreads(); }
    float mean = red[0] * (1.f / 128.f); __syncthreads();
    float dv = acc - mean;
    red[o] = dv * dv; __syncthreads();
    for (int s = 64; s > 0; s >>= 1) { if (o < s) red[o] += red[o + s]; __syncthreads(); }
    float var = red[0] * (1.f / 128.f);
    float y = dv / sqrtf(var + 1e-5f) * gv[o] + bev[o];
    outp[i * DD + o] = fmaxf(y, 0.f) + Pi[i * DD + o];
}

// ========== S[i][j] = sum_d proto[i][d]^2 * W1[j][d]  (for edge MLP) ==========
__global__ __launch_bounds__(128) void s8_kernel(const float* __restrict__ Pp,
                                                 const float* __restrict__ W1,
                                                 float* __restrict__ S) {
    __shared__ float red[8][128];
    int i = blockIdx.x, t = threadIdx.x;
    float a = Pp[i * DD + t];
    float a2 = a * a;
#pragma unroll
    for (int j = 0; j < 8; j++) red[j][t] = a2 * W1[j * DD + t];
    __syncthreads();
    for (int s = 64; s > 0; s >>= 1) {
        if (t < s) {
#pragma unroll
            for (int j = 0; j < 8; j++) red[j][t] += red[j][t + s];
        }
        __syncthreads();
    }
    if (t < 8) S[i * HH + t] = red[t][0];
}

// ======= fused edge MLP: pairwise sqdiff -> W1 -> instnorm -> relu -> W2 -> tanh
//         -> logits = tanh(..) * (last_edge + eps) * invtemp  (written to LG) =======
__global__ __launch_bounds__(256) void edge_mlp_kernel(const float* __restrict__ Pp,
                                                       const float* __restrict__ W1,
                                                       const float* __restrict__ b1,
                                                       const float* __restrict__ W2,
                                                       const float* __restrict__ b2v,
                                                       const float* __restrict__ S,
                                                       const float* __restrict__ LAST,
                                                       float invtemp,
                                                       float* __restrict__ LG) {
    __shared__ float Ais[128][33];   // [d][i] transposed tiles
    __shared__ float Aks[128][33];
    __shared__ float W1s[128][8];    // [d][j]
    __shared__ float Sis[32][8];
    __shared__ float Sks[32][8];
    __shared__ float W2s[8];
    __shared__ float b1s[8];
    __shared__ float b2s;

    int bi = blockIdx.y * 32, bk = blockIdx.x * 32;
    int t = threadIdx.x;
    for (int idx = t; idx < 4096; idx += 256) {
        int r = idx >> 7, c = idx & 127;
        Ais[c][r] = Pp[(bi + r) * DD + c];
        Aks[c][r] = Pp[(bk + r) * DD + c];
    }
    for (int idx = t; idx < HH * DD; idx += 256)
        W1s[idx & 127][idx >> 7] = W1[idx];
    {
        int r = t >> 3, j = t & 7;
        Sis[r][j] = S[(bi + r) * HH + j];
        Sks[r][j] = S[(bk + r) * HH + j];
    }
    if (t < 8) { W2s[t] = W2[t]; b1s[t] = b1[t]; }
    if (t == 0) b2s = b2v[0];
    __syncthreads();

    int tx = t & 15, ty = t >> 4;
    int i0 = 2 * ty, k0 = 2 * tx;
    float acc[2][2][8];
#pragma unroll
    for (int a = 0; a < 2; a++)
#pragma unroll
        for (int b = 0; b < 2; b++)
#pragma unroll
            for (int j = 0; j < 8; j++) acc[a][b][j] = 0.f;

#pragma unroll 4
    for (int d = 0; d < 128; d++) {
        float4 wa = *(const float4*)&W1s[d][0];
        float4 wb = *(const float4*)&W1s[d][4];
        float w[8] = {wa.x, wa.y, wa.z, wa.w, wb.x, wb.y, wb.z, wb.w};
        float ai0 = Ais[d][i0], ai1 = Ais[d][i0 + 1];
        float ak0 = Aks[d][k0], ak1 = Aks[d][k0 + 1];
        float p00 = ai0 * ak0, p01 = ai0 * ak1;
        float p10 = ai1 * ak0, p11 = ai1 * ak1;
#pragma unroll
        for (int j = 0; j < 8; j++) {
            acc[0][0][j] += p00 * w[j];
            acc[0][1][j] += p01 * w[j];
            acc[1][0][j] += p10 * w[j];
            acc[1][1][j] += p11 * w[j];
        }
    }

#pragma unroll
    for (int ii = 0; ii < 2; ii++)
#pragma unroll
        for (int kk = 0; kk < 2; kk++) {
            int gi = bi + i0 + ii, gk = bk + k0 + kk;
            bool diag = (gi == gk);
            float h[8];
            float mean = 0.f;
#pragma unroll
            for (int j = 0; j < 8; j++) {
                float v = diag ? b1s[j]
                               : (Sis[i0 + ii][j] + Sks[k0 + kk][j] - 2.f * acc[ii][kk][j] + b1s[j]);
                h[j] = v;
                mean += v;
            }
            mean *= 0.125f;
            float var = 0.f;
#pragma unroll
            for (int j = 0; j < 8; j++) { float dv = h[j] - mean; var += dv * dv; }
            var *= 0.125f;
            float inv = 1.f / sqrtf(var + 1e-5f);
            float sdot = b2s;
#pragma unroll
            for (int j = 0; j < 8; j++) {
                float r = fmaxf((h[j] - mean) * inv, 0.f);
                sdot += r * W2s[j];
            }
            float e = tanhf(sdot);
            LG[gi * NP + gk] = e * (LAST[gi * NP + gk] + 1e-8f) * invtemp;
        }
}

// ============================== launcher ==============================
extern "C" void kernel_launch(void* const* d_in, const int* in_sizes, int n_in,
                              void* d_out, int out_size) {
    const float* visual   = (const float*)d_in[0];
    const float* semantic = (const float*)d_in[1];
    const float* attr     = (const float*)d_in[2];
    const float* Wvn  = (const float*)d_in[3];
    const float* bvn  = (const float*)d_in[4];
    const float* gvn  = (const float*)d_in[5];
    const float* betavn = (const float*)d_in[6];
    const float* Wve1 = (const float*)d_in[7];
    const float* bve1 = (const float*)d_in[8];
    const float* Wve2 = (const float*)d_in[9];
    const float* bve2 = (const float*)d_in[10];
    const float* Wsn  = (const float*)d_in[11];
    const float* bsn  = (const float*)d_in[12];
    const float* gsn  = (const float*)d_in[13];
    const float* betasn = (const float*)d_in[14];
    const float* Wse1 = (const float*)d_in[15];
    const float* bse1 = (const float*)d_in[16];
    const float* Wse2 = (const float*)d_in[17];
    const float* bse2 = (const float*)d_in[18];

    float* out = (float*)d_out;
    float* vp  = out;                       // [768,128]
    float* sp  = out + NP * DD;             // [768,128]
    float* ve2 = out + 2 * NP * DD;         // [768,768]
    float* se2 = ve2 + NP * NP;             // [768,768]

    float *G, *VE, *SE, *LG, *P, *M, *S8, *NR;
    cudaGetSymbolAddress((void**)&G,  g_G);
    cudaGetSymbolAddress((void**)&VE, g_VE);
    cudaGetSymbolAddress((void**)&SE, g_SE);
    cudaGetSymbolAddress((void**)&LG, g_LG);
    cudaGetSymbolAddress((void**)&P,  g_P);
    cudaGetSymbolAddress((void**)&M,  g_M);
    cudaGetSymbolAddress((void**)&S8, g_S8);
    cudaGetSymbolAddress((void**)&NR, g_NRM);

    dim3 gTile(24, 24);

    // ve = init_edge(visual, 0.1)
    xxt_kernel<<<gTile, 256>>>(visual, DD, G);
    norms_kernel<<<3, 256>>>(G, NR);
    softmax_sim_kernel<<<NP, 256>>>(G, NR, 10.0f, VE);

    // se = init_edge(attribute, 0.1)
    xxt_kernel<<<gTile, 256>>>(attr, 312, G);
    norms_kernel<<<3, 256>>>(G, NR);
    softmax_sim_kernel<<<NP, 256>>>(G, NR, 10.0f, SE);

    // vp = node_update(visual, last=se, edge=ve)
    agg_kernel<<<24, 256>>>(VE, SE, visual, P, M);
    node_kernel<<<NP, 128>>>(M, P, Wvn, bvn, gvn, betavn, vp);

    // ve2 = edge_update(vp, ve, temp=10)
    s8_kernel<<<NP, 128>>>(vp, Wve1, S8);
    edge_mlp_kernel<<<gTile, 256>>>(vp, Wve1, bve1, Wve2, bve2, S8, VE, 0.1f, LG);
    softmax_row_kernel<<<NP, 256>>>(LG, ve2);

    // sp = node_update(semantic, last=ve2, edge=se)
    agg_kernel<<<24, 256>>>(SE, ve2, semantic, P, M);
    node_kernel<<<NP, 128>>>(M, P, Wsn, bsn, gsn, betasn, sp);

    // se2 = edge_update(sp, se, temp=10)
    s8_kernel<<<NP, 128>>>(sp, Wse1, S8);
    edge_mlp_kernel<<<gTile, 256>>>(sp, Wse1, bse1, Wse2, bse2, S8, SE, 0.1f, LG);
    softmax_row_kernel<<<NP, 256>>>(LG, se2);
}

// round 9
// speedup vs baseline: 1.3862x; 1.3862x over previous
#include <cuda_runtime.h>
#include <math.h>

#define NP 768
#define DD 128
#define HH 8

// ---- scratch (no allocs allowed; static device globals) ----
__device__ float g_G [NP*NP];   // visual gram, later reused as edge "e" buffer ET
__device__ float g_G2[NP*NP];   // attribute gram
__device__ float g_VE[NP*NP];
__device__ float g_SE[NP*NP];
__device__ float g_P [NP*DD];
__device__ float g_M [NP*DD];
__device__ float g_S8[NP*HH];
__device__ float g_NR0[NP];
__device__ float g_NR1[NP];

// ====== symmetric X@X^T for both inputs in one launch (z=0 visual K=128, z=1 attr K=312)
// 64x64 tiles, 4x4 micro-tile per thread, upper block-triangle only, mirrored writes.
__global__ __launch_bounds__(256) void xxt_sym_kernel(const float* __restrict__ X0,
                                                      const float* __restrict__ X1,
                                                      float* __restrict__ G0,
                                                      float* __restrict__ G1) {
    if (blockIdx.x < blockIdx.y) return;
    int z = blockIdx.z;
    const float* __restrict__ X = z ? X1 : X0;
    float* __restrict__ G = z ? G1 : G0;
    const int K = z ? 312 : 128;

    __shared__ __align__(16) float Xi[16][68];
    __shared__ __align__(16) float Xk[16][68];

    int bi = blockIdx.y * 64, bk = blockIdx.x * 64;
    bool offDiag = (blockIdx.x > blockIdx.y);
    int t = threadIdx.x, tx = t & 15, ty = t >> 4;

    float acc[4][4];
#pragma unroll
    for (int r = 0; r < 4; r++)
#pragma unroll
        for (int c = 0; c < 4; c++) acc[r][c] = 0.f;

    for (int k0 = 0; k0 < K; k0 += 16) {
        for (int idx = t; idx < 1024; idx += 256) {
            int r = idx >> 4, c = idx & 15;
            int kc = k0 + c;
            Xi[c][r] = (kc < K) ? X[(bi + r) * K + kc] : 0.f;
            Xk[c][r] = (kc < K) ? X[(bk + r) * K + kc] : 0.f;
        }
        __syncthreads();
#pragma unroll
        for (int kk = 0; kk < 16; kk++) {
            float4 a = *(const float4*)&Xi[kk][4 * ty];
            float4 b = *(const float4*)&Xk[kk][4 * tx];
            acc[0][0] += a.x * b.x; acc[0][1] += a.x * b.y; acc[0][2] += a.x * b.z; acc[0][3] += a.x * b.w;
            acc[1][0] += a.y * b.x; acc[1][1] += a.y * b.y; acc[1][2] += a.y * b.z; acc[1][3] += a.y * b.w;
            acc[2][0] += a.z * b.x; acc[2][1] += a.z * b.y; acc[2][2] += a.z * b.z; acc[2][3] += a.z * b.w;
            acc[3][0] += a.w * b.x; acc[3][1] += a.w * b.y; acc[3][2] += a.w * b.z; acc[3][3] += a.w * b.w;
        }
        __syncthreads();
    }
    int gk = bk + 4 * tx;
#pragma unroll
    for (int r = 0; r < 4; r++) {
        int gi = bi + 4 * ty + r;
        *(float4*)&G[gi * NP + gk] = make_float4(acc[r][0], acc[r][1], acc[r][2], acc[r][3]);
        if (offDiag) {
            G[(gk + 0) * NP + gi] = acc[r][0];
            G[(gk + 1) * NP + gi] = acc[r][1];
            G[(gk + 2) * NP + gi] = acc[r][2];
            G[(gk + 3) * NP + gi] = acc[r][3];
        }
    }
}

__global__ void norms2_kernel(const float* __restrict__ G0, const float* __restrict__ G1,
                              float* __restrict__ n0, float* __restrict__ n1) {
    int i = blockIdx.x * 256 + threadIdx.x;
    if (i < NP) n0[i] = sqrtf(G0[i * NP + i]);
    else { int j = i - NP; if (j < NP) n1[j] = sqrtf(G1[j * NP + j]); }
}

// ====== cosine-sim softmax for both grams in one launch (grid 768 x 2) ======
__global__ __launch_bounds__(256) void softmax_sim2_kernel(const float* __restrict__ G0,
                                                           const float* __restrict__ G1,
                                                           const float* __restrict__ n0,
                                                           const float* __restrict__ n1,
                                                           float* __restrict__ E0,
                                                           float* __restrict__ E1) {
    __shared__ float sh[256];
    int z = blockIdx.y;
    const float* __restrict__ G = z ? G1 : G0;
    const float* __restrict__ nrm = z ? n1 : n0;
    float* __restrict__ E = z ? E1 : E0;
    const float invtemp = 10.0f;  // 1 / INIT_TEMP

    int i = blockIdx.x, t = threadIdx.x;
    float ni = nrm[i];
    float l[3];
    float mx = -1e30f;
#pragma unroll
    for (int q = 0; q < 3; q++) {
        int c = t + q * 256;
        float den = fmaxf(ni * nrm[c], 1e-8f);
        l[q] = G[i * NP + c] / den * invtemp;
        mx = fmaxf(mx, l[q]);
    }
    sh[t] = mx; __syncthreads();
    for (int s = 128; s > 0; s >>= 1) { if (t < s) sh[t] = fmaxf(sh[t], sh[t + s]); __syncthreads(); }
    mx = sh[0]; __syncthreads();
    float sum = 0.f;
#pragma unroll
    for (int q = 0; q < 3; q++) { l[q] = expf(l[q] - mx); sum += l[q]; }
    sh[t] = sum; __syncthreads();
    for (int s = 128; s > 0; s >>= 1) { if (t < s) sh[t] += sh[t + s]; __syncthreads(); }
    float inv = 1.f / sh[0];
#pragma unroll
    for (int q = 0; q < 3; q++) E[i * NP + t + q * 256] = l[q] * inv;
}

// ====== edge softmax: logits = e * (last + eps) * invtemp, fused ======
__global__ __launch_bounds__(256) void softmax_edge_kernel(const float* __restrict__ ET,
                                                           const float* __restrict__ LAST,
                                                           float invtemp,
                                                           float* __restrict__ E) {
    __shared__ float sh[256];
    int i = blockIdx.x, t = threadIdx.x;
    float l[3];
    float mx = -1e30f;
#pragma unroll
    for (int q = 0; q < 3; q++) {
        int c = i * NP + t + q * 256;
        l[q] = ET[c] * (LAST[c] + 1e-8f) * invtemp;
        mx = fmaxf(mx, l[q]);
    }
    sh[t] = mx; __syncthreads();
    for (int s = 128; s > 0; s >>= 1) { if (t < s) sh[t] = fmaxf(sh[t], sh[t + s]); __syncthreads(); }
    mx = sh[0]; __syncthreads();
    float sum = 0.f;
#pragma unroll
    for (int q = 0; q < 3; q++) { l[q] = expf(l[q] - mx); sum += l[q]; }
    sh[t] = sum; __syncthreads();
    for (int s = 128; s > 0; s >>= 1) { if (t < s) sh[t] += sh[t + s]; __syncthreads(); }
    float inv = 1.f / sh[0];
#pragma unroll
    for (int q = 0; q < 3; q++) E[i * NP + t + q * 256] = l[q] * inv;
}

// ===== aggregation: P = E @ V ; M = (E + L) @ V, grid (48, 4) =====
// 16-row x 32-col tiles; 256 threads, each thread = 1 row x 2 cols.
__global__ __launch_bounds__(256) void agg_kernel(const float* __restrict__ E,
                                                  const float* __restrict__ L,
                                                  const float* __restrict__ V,
                                                  float* __restrict__ Pout,
                                                  float* __restrict__ Mout) {
    __shared__ float Es[16][33];
    __shared__ float Ls[16][33];
    __shared__ __align__(16) float Vs[32][34];
    int bi = blockIdx.x * 16, bc = blockIdx.y * 32;
    int t = threadIdx.x, tx = t & 15, ty = t >> 4;
    float p0 = 0.f, p1 = 0.f, m0 = 0.f, m1 = 0.f;

    for (int k0 = 0; k0 < NP; k0 += 32) {
        for (int idx = t; idx < 512; idx += 256) {
            int r = idx >> 5, c = idx & 31;
            Es[r][c] = E[(bi + r) * NP + k0 + c];
            Ls[r][c] = L[(bi + r) * NP + k0 + c];
        }
        for (int idx = t; idx < 1024; idx += 256) {
            int r = idx >> 5, c = idx & 31;
            Vs[r][c] = V[(k0 + r) * DD + bc + c];
        }
        __syncthreads();
#pragma unroll 8
        for (int kk = 0; kk < 32; kk++) {
            float e = Es[ty][kk];
            float s = e + Ls[ty][kk];
            float v0 = Vs[kk][2 * tx], v1 = Vs[kk][2 * tx + 1];
            p0 += e * v0; p1 += e * v1;
            m0 += s * v0; m1 += s * v1;
        }
        __syncthreads();
    }
    int row = bi + ty, col = bc + 2 * tx;
    Pout[row * DD + col] = p0; Pout[row * DD + col + 1] = p1;
    Mout[row * DD + col] = m0; Mout[row * DD + col + 1] = m1;
}

// ======== node update: out = relu(LN(M @ W^T + b, g, beta)) + P  ========
__global__ __launch_bounds__(128) void node_kernel(const float* __restrict__ Mi,
                                                   const float* __restrict__ Pi,
                                                   const float* __restrict__ W,
                                                   const float* __restrict__ bv,
                                                   const float* __restrict__ gv,
                                                   const float* __restrict__ bev,
                                                   float* __restrict__ outp) {
    __shared__ float ms[128];
    __shared__ float red[128];
    int i = blockIdx.x, o = threadIdx.x;
    ms[o] = Mi[i * DD + o];
    __syncthreads();
    float acc = bv[o];
    const float4* w4 = (const float4*)(W + o * DD);
    const float4* m4 = (const float4*)ms;
#pragma unroll
    for (int q = 0; q < 32; q++) {
        float4 w = w4[q];
        float4 m = m4[q];
        acc += w.x * m.x + w.y * m.y + w.z * m.z + w.w * m.w;
    }
    red[o] = acc; __syncthreads();
    for (int s = 64; s > 0; s >>= 1) { if (o < s) red[o] += red[o + s]; __syncthreads(); }
    float mean = red[0] * (1.f / 128.f); __syncthreads();
    float dv = acc - mean;
    red[o] = dv * dv; __syncthreads();
    for (int s = 64; s > 0; s >>= 1) { if (o < s) red[o] += red[o + s]; __syncthreads(); }
    float var = red[0] * (1.f / 128.f);
    float y = dv / sqrtf(var + 1e-5f) * gv[o] + bev[o];
    outp[i * DD + o] = fmaxf(y, 0.f) + Pi[i * DD + o];
}

// ========== S[i][j] = sum_d proto[i][d]^2 * W1[j][d]  (for edge MLP) ==========
__global__ __launch_bounds__(128) void s8_kernel(const float* __restrict__ Pp,
                                                 const float* __restrict__ W1,
                                                 float* __restrict__ S) {
    __shared__ float red[8][128];
    int i = blockIdx.x, t = threadIdx.x;
    float a = Pp[i * DD + t];
    float a2 = a * a;
#pragma unroll
    for (int j = 0; j < 8; j++) red[j][t] = a2 * W1[j * DD + t];
    __syncthreads();
    for (int s = 64; s > 0; s >>= 1) {
        if (t < s) {
#pragma unroll
            for (int j = 0; j < 8; j++) red[j][t] += red[j][t + s];
        }
        __syncthreads();
    }
    if (t < 8) S[i * HH + t] = red[t][0];
}

// ======= fused edge MLP (symmetric: upper block-triangle only) =======
// writes e = tanh(MLP(pairwise sqdiff)) to ET (symmetric, mirrored)
__global__ __launch_bounds__(256) void edge_mlp_kernel(const float* __restrict__ Pp,
                                                       const float* __restrict__ W1,
                                                       const float* __restrict__ b1,
                                                       const float* __restrict__ W2,
                                                       const float* __restrict__ b2v,
                                                       const float* __restrict__ S,
                                                       float* __restrict__ ET) {
    if (blockIdx.x < blockIdx.y) return;

    __shared__ float Ais[128][33];   // [d][i] transposed tiles
    __shared__ float Aks[128][33];
    __shared__ __align__(16) float W1s[128][8];    // [d][j]
    __shared__ float Sis[32][8];
    __shared__ float Sks[32][8];
    __shared__ float W2s[8];
    __shared__ float b1s[8];
    __shared__ float b2s;

    int bi = blockIdx.y * 32, bk = blockIdx.x * 32;
    bool offDiag = (blockIdx.x > blockIdx.y);
    int t = threadIdx.x;
    for (int idx = t; idx < 4096; idx += 256) {
        int r = idx >> 7, c = idx & 127;
        Ais[c][r] = Pp[(bi + r) * DD + c];
        Aks[c][r] = Pp[(bk + r) * DD + c];
    }
    for (int idx = t; idx < HH * DD; idx += 256)
        W1s[idx & 127][idx >> 7] = W1[idx];
    {
        int r = t >> 3, j = t & 7;
        Sis[r][j] = S[(bi + r) * HH + j];
        Sks[r][j] = S[(bk + r) * HH + j];
    }
    if (t < 8) { W2s[t] = W2[t]; b1s[t] = b1[t]; }
    if (t == 0) b2s = b2v[0];
    __syncthreads();

    int tx = t & 15, ty = t >> 4;
    int i0 = 2 * ty, k0 = 2 * tx;
    float acc[2][2][8];
#pragma unroll
    for (int a = 0; a < 2; a++)
#pragma unroll
        for (int b = 0; b < 2; b++)
#pragma unroll
            for (int j = 0; j < 8; j++) acc[a][b][j] = 0.f;

#pragma unroll 4
    for (int d = 0; d < 128; d++) {
        float4 wa = *(const float4*)&W1s[d][0];
        float4 wb = *(const float4*)&W1s[d][4];
        float w[8] = {wa.x, wa.y, wa.z, wa.w, wb.x, wb.y, wb.z, wb.w};
        float ai0 = Ais[d][i0], ai1 = Ais[d][i0 + 1];
        float ak0 = Aks[d][k0], ak1 = Aks[d][k0 + 1];
        float p00 = ai0 * ak0, p01 = ai0 * ak1;
        float p10 = ai1 * ak0, p11 = ai1 * ak1;
#pragma unroll
        for (int j = 0; j < 8; j++) {
            acc[0][0][j] += p00 * w[j];
            acc[0][1][j] += p01 * w[j];
            acc[1][0][j] += p10 * w[j];
            acc[1][1][j] += p11 * w[j];
        }
    }

#pragma unroll
    for (int ii = 0; ii < 2; ii++)
#pragma unroll
        for (int kk = 0; kk < 2; kk++) {
            int gi = bi + i0 + ii, gk = bk + k0 + kk;
            bool diag = (gi == gk);
            float h[8];
            float mean = 0.f;
#pragma unroll
            for (int j = 0; j < 8; j++) {
                float v = diag ? b1s[j]
                               : (Sis[i0 + ii][j] + Sks[k0 + kk][j] - 2.f * acc[ii][kk][j] + b1s[j]);
                h[j] = v;
                mean += v;
            }
            mean *= 0.125f;
            float var = 0.f;
#pragma unroll
            for (int j = 0; j < 8; j++) { float dv = h[j] - mean; var += dv * dv; }
            var *= 0.125f;
            float inv = 1.f / sqrtf(var + 1e-5f);
            float sdot = b2s;
#pragma unroll
            for (int j = 0; j < 8; j++) {
                float r = fmaxf((h[j] - mean) * inv, 0.f);
                sdot += r * W2s[j];
            }
            float e = tanhf(sdot);
            ET[gi * NP + gk] = e;
            if (offDiag) ET[gk * NP + gi] = e;
        }
}

// ============================== launcher ==============================
extern "C" void kernel_launch(void* const* d_in, const int* in_sizes, int n_in,
                              void* d_out, int out_size) {
    const float* visual   = (const float*)d_in[0];
    const float* semantic = (const float*)d_in[1];
    const float* attr     = (const float*)d_in[2];
    const float* Wvn  = (const float*)d_in[3];
    const float* bvn  = (const float*)d_in[4];
    const float* gvn  = (const float*)d_in[5];
    const float* betavn = (const float*)d_in[6];
    const float* Wve1 = (const float*)d_in[7];
    const float* bve1 = (const float*)d_in[8];
    const float* Wve2 = (const float*)d_in[9];
    const float* bve2 = (const float*)d_in[10];
    const float* Wsn  = (const float*)d_in[11];
    const float* bsn  = (const float*)d_in[12];
    const float* gsn  = (const float*)d_in[13];
    const float* betasn = (const float*)d_in[14];
    const float* Wse1 = (const float*)d_in[15];
    const float* bse1 = (const float*)d_in[16];
    const float* Wse2 = (const float*)d_in[17];
    const float* bse2 = (const float*)d_in[18];

    float* out = (float*)d_out;
    float* vp  = out;                       // [768,128]
    float* sp  = out + NP * DD;             // [768,128]
    float* ve2 = out + 2 * NP * DD;         // [768,768]
    float* se2 = ve2 + NP * NP;             // [768,768]

    float *G, *G2, *VE, *SE, *P, *M, *S8, *NR0, *NR1;
    cudaGetSymbolAddress((void**)&G,   g_G);
    cudaGetSymbolAddress((void**)&G2,  g_G2);
    cudaGetSymbolAddress((void**)&VE,  g_VE);
    cudaGetSymbolAddress((void**)&SE,  g_SE);
    cudaGetSymbolAddress((void**)&P,   g_P);
    cudaGetSymbolAddress((void**)&M,   g_M);
    cudaGetSymbolAddress((void**)&S8,  g_S8);
    cudaGetSymbolAddress((void**)&NR0, g_NR0);
    cudaGetSymbolAddress((void**)&NR1, g_NR1);

    float* ET = G;  // reuse visual gram buffer once VE is computed

    // ve = init_edge(visual, 0.1); se = init_edge(attribute, 0.1) — fused launches
    xxt_sym_kernel<<<dim3(12, 12, 2), 256>>>(visual, attr, G, G2);
    norms2_kernel<<<6, 256>>>(G, G2, NR0, NR1);
    softmax_sim2_kernel<<<dim3(NP, 2), 256>>>(G, G2, NR0, NR1, VE, SE);

    // vp = node_update(visual, last=se, edge=ve)
    agg_kernel<<<dim3(48, 4), 256>>>(VE, SE, visual, P, M);
    node_kernel<<<NP, 128>>>(M, P, Wvn, bvn, gvn, betavn, vp);

    // ve2 = edge_update(vp, ve, temp=10)
    s8_kernel<<<NP, 128>>>(vp, Wve1, S8);
    edge_mlp_kernel<<<dim3(24, 24), 256>>>(vp, Wve1, bve1, Wve2, bve2, S8, ET);
    softmax_edge_kernel<<<NP, 256>>>(ET, VE, 0.1f, ve2);

    // sp = node_update(semantic, last=ve2, edge=se)
    agg_kernel<<<dim3(48, 4), 256>>>(SE, ve2, semantic, P, M);
    node_kernel<<<NP, 128>>>(M, P, Wsn, bsn, gsn, betasn, sp);

    // se2 = edge_update(sp, se, temp=10)
    s8_kernel<<<NP, 128>>>(sp, Wse1, S8);
    edge_mlp_kernel<<<dim3(24, 24), 256>>>(sp, Wse1, bse1, Wse2, bse2, S8, ET);
    softmax_edge_kernel<<<NP, 256>>>(ET, SE, 0.1f, se2);
}

// round 11
// speedup vs baseline: 1.7082x; 1.2322x over previous
#include <cuda_runtime.h>
#include <math.h>

#define NP 768
#define DD 128
#define HH 8

// ---- scratch (no allocs allowed; static device globals) ----
__device__ float g_G [NP*NP];   // visual gram, later reused as edge "e" buffer ET
__device__ float g_G2[NP*NP];   // attribute gram
__device__ float g_VE[NP*NP];
__device__ float g_SE[NP*NP];
__device__ float g_P [NP*DD];
__device__ float g_M [NP*DD];
__device__ float g_S8[NP*HH];
__device__ float g_NR0[NP];
__device__ float g_NR1[NP];

// ====== symmetric X@X^T for both inputs in one launch (z=0 visual K=128, z=1 attr K=312)
// 64x64 tiles, 4x4 micro-tile per thread, upper block-triangle only, mirrored writes.
__global__ __launch_bounds__(256) void xxt_sym_kernel(const float* __restrict__ X0,
                                                      const float* __restrict__ X1,
                                                      float* __restrict__ G0,
                                                      float* __restrict__ G1) {
    if (blockIdx.x < blockIdx.y) return;
    int z = blockIdx.z;
    const float* __restrict__ X = z ? X1 : X0;
    float* __restrict__ G = z ? G1 : G0;
    const int K = z ? 312 : 128;

    __shared__ __align__(16) float Xi[16][68];
    __shared__ __align__(16) float Xk[16][68];

    int bi = blockIdx.y * 64, bk = blockIdx.x * 64;
    bool offDiag = (blockIdx.x > blockIdx.y);
    int t = threadIdx.x, tx = t & 15, ty = t >> 4;

    float acc[4][4];
#pragma unroll
    for (int r = 0; r < 4; r++)
#pragma unroll
        for (int c = 0; c < 4; c++) acc[r][c] = 0.f;

    for (int k0 = 0; k0 < K; k0 += 16) {
        for (int idx = t; idx < 1024; idx += 256) {
            int r = idx >> 4, c = idx & 15;
            int kc = k0 + c;
            Xi[c][r] = (kc < K) ? X[(bi + r) * K + kc] : 0.f;
            Xk[c][r] = (kc < K) ? X[(bk + r) * K + kc] : 0.f;
        }
        __syncthreads();
#pragma unroll
        for (int kk = 0; kk < 16; kk++) {
            float4 a = *(const float4*)&Xi[kk][4 * ty];
            float4 b = *(const float4*)&Xk[kk][4 * tx];
            acc[0][0] += a.x * b.x; acc[0][1] += a.x * b.y; acc[0][2] += a.x * b.z; acc[0][3] += a.x * b.w;
            acc[1][0] += a.y * b.x; acc[1][1] += a.y * b.y; acc[1][2] += a.y * b.z; acc[1][3] += a.y * b.w;
            acc[2][0] += a.z * b.x; acc[2][1] += a.z * b.y; acc[2][2] += a.z * b.z; acc[2][3] += a.z * b.w;
            acc[3][0] += a.w * b.x; acc[3][1] += a.w * b.y; acc[3][2] += a.w * b.z; acc[3][3] += a.w * b.w;
        }
        __syncthreads();
    }
    int gk = bk + 4 * tx;
#pragma unroll
    for (int r = 0; r < 4; r++) {
        int gi = bi + 4 * ty + r;
        *(float4*)&G[gi * NP + gk] = make_float4(acc[r][0], acc[r][1], acc[r][2], acc[r][3]);
        if (offDiag) {
            G[(gk + 0) * NP + gi] = acc[r][0];
            G[(gk + 1) * NP + gi] = acc[r][1];
            G[(gk + 2) * NP + gi] = acc[r][2];
            G[(gk + 3) * NP + gi] = acc[r][3];
        }
    }
}

__global__ void norms2_kernel(const float* __restrict__ G0, const float* __restrict__ G1,
                              float* __restrict__ n0, float* __restrict__ n1) {
    int i = blockIdx.x * 256 + threadIdx.x;
    if (i < NP) n0[i] = sqrtf(G0[i * NP + i]);
    else { int j = i - NP; if (j < NP) n1[j] = sqrtf(G1[j * NP + j]); }
}

// ====== cosine-sim softmax for both grams in one launch (grid 768 x 2) ======
__global__ __launch_bounds__(256) void softmax_sim2_kernel(const float* __restrict__ G0,
                                                           const float* __restrict__ G1,
                                                           const float* __restrict__ n0,
                                                           const float* __restrict__ n1,
                                                           float* __restrict__ E0,
                                                           float* __restrict__ E1) {
    __shared__ float sh[256];
    int z = blockIdx.y;
    const float* __restrict__ G = z ? G1 : G0;
    const float* __restrict__ nrm = z ? n1 : n0;
    float* __restrict__ E = z ? E1 : E0;
    const float invtemp = 10.0f;  // 1 / INIT_TEMP

    int i = blockIdx.x, t = threadIdx.x;
    float ni = nrm[i];
    float l[3];
    float mx = -1e30f;
#pragma unroll
    for (int q = 0; q < 3; q++) {
        int c = t + q * 256;
        float den = fmaxf(ni * nrm[c], 1e-8f);
        l[q] = G[i * NP + c] / den * invtemp;
        mx = fmaxf(mx, l[q]);
    }
    sh[t] = mx; __syncthreads();
    for (int s = 128; s > 0; s >>= 1) { if (t < s) sh[t] = fmaxf(sh[t], sh[t + s]); __syncthreads(); }
    mx = sh[0]; __syncthreads();
    float sum = 0.f;
#pragma unroll
    for (int q = 0; q < 3; q++) { l[q] = expf(l[q] - mx); sum += l[q]; }
    sh[t] = sum; __syncthreads();
    for (int s = 128; s > 0; s >>= 1) { if (t < s) sh[t] += sh[t + s]; __syncthreads(); }
    float inv = 1.f / sh[0];
#pragma unroll
    for (int q = 0; q < 3; q++) E[i * NP + t + q * 256] = l[q] * inv;
}

// ====== edge softmax: logits = e * (last + eps) * invtemp, fused ======
__global__ __launch_bounds__(256) void softmax_edge_kernel(const float* __restrict__ ET,
                                                           const float* __restrict__ LAST,
                                                           float invtemp,
                                                           float* __restrict__ E) {
    __shared__ float sh[256];
    int i = blockIdx.x, t = threadIdx.x;
    float l[3];
    float mx = -1e30f;
#pragma unroll
    for (int q = 0; q < 3; q++) {
        int c = i * NP + t + q * 256;
        l[q] = ET[c] * (LAST[c] + 1e-8f) * invtemp;
        mx = fmaxf(mx, l[q]);
    }
    sh[t] = mx; __syncthreads();
    for (int s = 128; s > 0; s >>= 1) { if (t < s) sh[t] = fmaxf(sh[t], sh[t + s]); __syncthreads(); }
    mx = sh[0]; __syncthreads();
    float sum = 0.f;
#pragma unroll
    for (int q = 0; q < 3; q++) { l[q] = expf(l[q] - mx); sum += l[q]; }
    sh[t] = sum; __syncthreads();
    for (int s = 128; s > 0; s >>= 1) { if (t < s) sh[t] += sh[t + s]; __syncthreads(); }
    float inv = 1.f / sh[0];
#pragma unroll
    for (int q = 0; q < 3; q++) E[i * NP + t + q * 256] = l[q] * inv;
}

// ===== aggregation v2: P = E @ V ; M = (E + L) @ V =====
// grid = 96 blocks, each owns 8 output rows x all 128 cols.
// E,L rows preloaded ONCE to smem transposed (S=E+L precomputed);
// V streamed in 64-row chunks. Thread = 1 row x 4 cols.
__global__ __launch_bounds__(256) void agg_kernel(const float* __restrict__ E,
                                                  const float* __restrict__ L,
                                                  const float* __restrict__ V,
                                                  float* __restrict__ Pout,
                                                  float* __restrict__ Mout) {
    __shared__ float Et[NP][9];               // [k][row], pad 9 -> conflict-free fill
    __shared__ float St[NP][9];               // E + L
    __shared__ __align__(16) float Vs[64][128];

    int bi = blockIdx.x * 8;
    int t = threadIdx.x;
    int tx = t & 31;          // col group: 4 cols each -> 128 cols
    int ty = t >> 5;          // row 0..7 (uniform per warp -> smem broadcast reads)

    // preload E/L rows for this block, transposed, S = E + L
#pragma unroll
    for (int r = 0; r < 8; r++) {
        for (int k = t; k < NP; k += 256) {
            float e = E[(bi + r) * NP + k];
            float l = L[(bi + r) * NP + k];
            Et[k][r] = e;
            St[k][r] = e + l;
        }
    }

    float4 p = make_float4(0.f, 0.f, 0.f, 0.f);
    float4 m = make_float4(0.f, 0.f, 0.f, 0.f);

    for (int k0 = 0; k0 < NP; k0 += 64) {
        __syncthreads();
        // load V chunk [64][128]
        for (int idx = t; idx < 2048; idx += 256) {
            int kk = idx >> 5, c4 = idx & 31;
            *(float4*)&Vs[kk][c4 * 4] = *(const float4*)&V[(k0 + kk) * DD + c4 * 4];
        }
        __syncthreads();
#pragma unroll 16
        for (int kk = 0; kk < 64; kk++) {
            float e = Et[k0 + kk][ty];
            float s = St[k0 + kk][ty];
            float4 v = *(const float4*)&Vs[kk][4 * tx];
            p.x += e * v.x; p.y += e * v.y; p.z += e * v.z; p.w += e * v.w;
            m.x += s * v.x; m.y += s * v.y; m.z += s * v.z; m.w += s * v.w;
        }
    }
    int row = bi + ty, col = 4 * tx;
    *(float4*)&Pout[row * DD + col] = p;
    *(float4*)&Mout[row * DD + col] = m;
}

// ======== node update: out = relu(LN(M @ W^T + b, g, beta)) + P  ========
__global__ __launch_bounds__(128) void node_kernel(const float* __restrict__ Mi,
                                                   const float* __restrict__ Pi,
                                                   const float* __restrict__ W,
                                                   const float* __restrict__ bv,
                                                   const float* __restrict__ gv,
                                                   const float* __restrict__ bev,
                                                   float* __restrict__ outp) {
    __shared__ float ms[128];
    __shared__ float red[128];
    int i = blockIdx.x, o = threadIdx.x;
    ms[o] = Mi[i * DD + o];
    __syncthreads();
    float acc = bv[o];
    const float4* w4 = (const float4*)(W + o * DD);
    const float4* m4 = (const float4*)ms;
#pragma unroll
    for (int q = 0; q < 32; q++) {
        float4 w = w4[q];
        float4 m = m4[q];
        acc += w.x * m.x + w.y * m.y + w.z * m.z + w.w * m.w;
    }
    red[o] = acc; __syncthreads();
    for (int s = 64; s > 0; s >>= 1) { if (o < s) red[o] += red[o + s]; __syncthreads(); }
    float mean = red[0] * (1.f / 128.f); __syncthreads();
    float dv = acc - mean;
    red[o] = dv * dv; __syncthreads();
    for (int s = 64; s > 0; s >>= 1) { if (o < s) red[o] += red[o + s]; __syncthreads(); }
    float var = red[0] * (1.f / 128.f);
    float y = dv / sqrtf(var + 1e-5f) * gv[o] + bev[o];
    outp[i * DD + o] = fmaxf(y, 0.f) + Pi[i * DD + o];
}

// ========== S[i][j] = sum_d proto[i][d]^2 * W1[j][d]  (for edge MLP) ==========
__global__ __launch_bounds__(128) void s8_kernel(const float* __restrict__ Pp,
                                                 const float* __restrict__ W1,
                                                 float* __restrict__ S) {
    __shared__ float red[8][128];
    int i = blockIdx.x, t = threadIdx.x;
    float a = Pp[i * DD + t];
    float a2 = a * a;
#pragma unroll
    for (int j = 0; j < 8; j++) red[j][t] = a2 * W1[j * DD + t];
    __syncthreads();
    for (int s = 64; s > 0; s >>= 1) {
        if (t < s) {
#pragma unroll
            for (int j = 0; j < 8; j++) red[j][t] += red[j][t + s];
        }
        __syncthreads();
    }
    if (t < 8) S[i * HH + t] = red[t][0];
}

// ======= fused edge MLP (symmetric: upper block-triangle only) =======
// writes e = tanh(MLP(pairwise sqdiff)) to ET (symmetric, mirrored)
__global__ __launch_bounds__(256) void edge_mlp_kernel(const float* __restrict__ Pp,
                                                       const float* __restrict__ W1,
                                                       const float* __restrict__ b1,
                                                       const float* __restrict__ W2,
                                                       const float* __restrict__ b2v,
                                                       const float* __restrict__ S,
                                                       float* __restrict__ ET) {
    if (blockIdx.x < blockIdx.y) return;

    __shared__ float Ais[128][33];   // [d][i] transposed tiles
    __shared__ float Aks[128][33];
    __shared__ __align__(16) float W1s[128][8];    // [d][j]
    __shared__ float Sis[32][8];
    __shared__ float Sks[32][8];
    __shared__ float W2s[8];
    __shared__ float b1s[8];
    __shared__ float b2s;

    int bi = blockIdx.y * 32, bk = blockIdx.x * 32;
    bool offDiag = (blockIdx.x > blockIdx.y);
    int t = threadIdx.x;
    for (int idx = t; idx < 4096; idx += 256) {
        int r = idx >> 7, c = idx & 127;
        Ais[c][r] = Pp[(bi + r) * DD + c];
        Aks[c][r] = Pp[(bk + r) * DD + c];
    }
    for (int idx = t; idx < HH * DD; idx += 256)
        W1s[idx & 127][idx >> 7] = W1[idx];
    {
        int r = t >> 3, j = t & 7;
        Sis[r][j] = S[(bi + r) * HH + j];
        Sks[r][j] = S[(bk + r) * HH + j];
    }
    if (t < 8) { W2s[t] = W2[t]; b1s[t] = b1[t]; }
    if (t == 0) b2s = b2v[0];
    __syncthreads();

    int tx = t & 15, ty = t >> 4;
    int i0 = 2 * ty, k0 = 2 * tx;
    float acc[2][2][8];
#pragma unroll
    for (int a = 0; a < 2; a++)
#pragma unroll
        for (int b = 0; b < 2; b++)
#pragma unroll
            for (int j = 0; j < 8; j++) acc[a][b][j] = 0.f;

#pragma unroll 4
    for (int d = 0; d < 128; d++) {
        float4 wa = *(const float4*)&W1s[d][0];
        float4 wb = *(const float4*)&W1s[d][4];
        float w[8] = {wa.x, wa.y, wa.z, wa.w, wb.x, wb.y, wb.z, wb.w};
        float ai0 = Ais[d][i0], ai1 = Ais[d][i0 + 1];
        float ak0 = Aks[d][k0], ak1 = Aks[d][k0 + 1];
        float p00 = ai0 * ak0, p01 = ai0 * ak1;
        float p10 = ai1 * ak0, p11 = ai1 * ak1;
#pragma unroll
        for (int j = 0; j < 8; j++) {
            acc[0][0][j] += p00 * w[j];
            acc[0][1][j] += p01 * w[j];
            acc[1][0][j] += p10 * w[j];
            acc[1][1][j] += p11 * w[j];
        }
    }

#pragma unroll
    for (int ii = 0; ii < 2; ii++)
#pragma unroll
        for (int kk = 0; kk < 2; kk++) {
            int gi = bi + i0 + ii, gk = bk + k0 + kk;
            bool diag = (gi == gk);
            float h[8];
            float mean = 0.f;
#pragma unroll
            for (int j = 0; j < 8; j++) {
                float v = diag ? b1s[j]
                               : (Sis[i0 + ii][j] + Sks[k0 + kk][j] - 2.f * acc[ii][kk][j] + b1s[j]);
                h[j] = v;
                mean += v;
            }
            mean *= 0.125f;
            float var = 0.f;
#pragma unroll
            for (int j = 0; j < 8; j++) { float dv = h[j] - mean; var += dv * dv; }
            var *= 0.125f;
            float inv = 1.f / sqrtf(var + 1e-5f);
            float sdot = b2s;
#pragma unroll
            for (int j = 0; j < 8; j++) {
                float r = fmaxf((h[j] - mean) * inv, 0.f);
                sdot += r * W2s[j];
            }
            float e = tanhf(sdot);
            ET[gi * NP + gk] = e;
            if (offDiag) ET[gk * NP + gi] = e;
        }
}

// ============================== launcher ==============================
extern "C" void kernel_launch(void* const* d_in, const int* in_sizes, int n_in,
                              void* d_out, int out_size) {
    const float* visual   = (const float*)d_in[0];
    const float* semantic = (const float*)d_in[1];
    const float* attr     = (const float*)d_in[2];
    const float* Wvn  = (const float*)d_in[3];
    const float* bvn  = (const float*)d_in[4];
    const float* gvn  = (const float*)d_in[5];
    const float* betavn = (const float*)d_in[6];
    const float* Wve1 = (const float*)d_in[7];
    const float* bve1 = (const float*)d_in[8];
    const float* Wve2 = (const float*)d_in[9];
    const float* bve2 = (const float*)d_in[10];
    const float* Wsn  = (const float*)d_in[11];
    const float* bsn  = (const float*)d_in[12];
    const float* gsn  = (const float*)d_in[13];
    const float* betasn = (const float*)d_in[14];
    const float* Wse1 = (const float*)d_in[15];
    const float* bse1 = (const float*)d_in[16];
    const float* Wse2 = (const float*)d_in[17];
    const float* bse2 = (const float*)d_in[18];

    float* out = (float*)d_out;
    float* vp  = out;                       // [768,128]
    float* sp  = out + NP * DD;             // [768,128]
    float* ve2 = out + 2 * NP * DD;         // [768,768]
    float* se2 = ve2 + NP * NP;             // [768,768]

    float *G, *G2, *VE, *SE, *P, *M, *S8, *NR0, *NR1;
    cudaGetSymbolAddress((void**)&G,   g_G);
    cudaGetSymbolAddress((void**)&G2,  g_G2);
    cudaGetSymbolAddress((void**)&VE,  g_VE);
    cudaGetSymbolAddress((void**)&SE,  g_SE);
    cudaGetSymbolAddress((void**)&P,   g_P);
    cudaGetSymbolAddress((void**)&M,   g_M);
    cudaGetSymbolAddress((void**)&S8,  g_S8);
    cudaGetSymbolAddress((void**)&NR0, g_NR0);
    cudaGetSymbolAddress((void**)&NR1, g_NR1);

    float* ET = G;  // reuse visual gram buffer once VE is computed

    // ve = init_edge(visual, 0.1); se = init_edge(attribute, 0.1) — fused launches
    xxt_sym_kernel<<<dim3(12, 12, 2), 256>>>(visual, attr, G, G2);
    norms2_kernel<<<6, 256>>>(G, G2, NR0, NR1);
    softmax_sim2_kernel<<<dim3(NP, 2), 256>>>(G, G2, NR0, NR1, VE, SE);

    // vp = node_update(visual, last=se, edge=ve)
    agg_kernel<<<96, 256>>>(VE, SE, visual, P, M);
    node_kernel<<<NP, 128>>>(M, P, Wvn, bvn, gvn, betavn, vp);

    // ve2 = edge_update(vp, ve, temp=10)
    s8_kernel<<<NP, 128>>>(vp, Wve1, S8);
    edge_mlp_kernel<<<dim3(24, 24), 256>>>(vp, Wve1, bve1, Wve2, bve2, S8, ET);
    softmax_edge_kernel<<<NP, 256>>>(ET, VE, 0.1f, ve2);

    // sp = node_update(semantic, last=ve2, edge=se)
    agg_kernel<<<96, 256>>>(SE, ve2, semantic, P, M);
    node_kernel<<<NP, 128>>>(M, P, Wsn, bsn, gsn, betasn, sp);

    // se2 = edge_update(sp, se, temp=10)
    s8_kernel<<<NP, 128>>>(sp, Wse1, S8);
    edge_mlp_kernel<<<dim3(24, 24), 256>>>(sp, Wse1, bse1, Wse2, bse2, S8, ET);
    softmax_edge_kernel<<<NP, 256>>>(ET, SE, 0.1f, se2);
}